// round 1
// baseline (speedup 1.0000x reference)
#include <cuda_runtime.h>
#include <cstdint>

#define C      128
#define C4     32
#define GMAX   64
#define LNUM   3
#define NCAP   100000
#define NEG    0.01f
#define EPSV   1e-5f

// ---------------- static scratch (no dynamic allocation allowed) ----------------
__device__ float g_xw  [(size_t)NCAP * C];   // x @ W
__device__ float g_agg [(size_t)NCAP * C];   // aggregation buffer (init = xw*dinv^2 + b)
__device__ float g_deg [NCAP];
__device__ float g_dinv[NCAP];
__device__ float g_cnt   [GMAX];
__device__ float g_cntinv[GMAX];
__device__ float g_ssum[GMAX * C];
__device__ float g_ssq [GMAX * C];
__device__ float g_A   [GMAX * C];
__device__ float g_B   [GMAX * C];

// ---------------- prep: degree + per-graph counts ----------------
__global__ void k_zero_prep(int N) {
    int i = blockIdx.x * blockDim.x + threadIdx.x;
    if (i < N)    g_deg[i] = 0.f;
    if (i < GMAX) g_cnt[i] = 0.f;
}

__global__ void k_count(const int* __restrict__ ei, const int* __restrict__ batch,
                        int E, int N) {
    int i = blockIdx.x * blockDim.x + threadIdx.x;
    if (i < E) atomicAdd(&g_deg[ei[E + i]], 1.0f);
    if (i < N) atomicAdd(&g_cnt[batch[i]], 1.0f);
}

__global__ void k_finprep(int N) {
    int i = blockIdx.x * blockDim.x + threadIdx.x;
    if (i < N)    g_dinv[i]   = rsqrtf(g_deg[i] + 1.0f);
    if (i < GMAX) g_cntinv[i] = 1.0f / fmaxf(g_cnt[i], 1.0f);
}

// ---------------- GEMM: xw = X @ W ; agg = xw*dinv^2 + bias ----------------
// Block: 256 threads, 32 rows/block. Thread (row=tid>>3, cg=tid&7) computes
// 8 float2 column-pairs at cols {2*cg + 16*j}. Uses packed fma.rn.f32x2.
__global__ void __launch_bounds__(256, 2)
k_gemm(const float* __restrict__ X, const float* __restrict__ W,
       const float* __restrict__ bias, int N) {
    __shared__ float Ws[C * C];        // 64 KB
    __shared__ float Xs[32 * 129];     // padded to kill bank conflicts
    int tid  = threadIdx.x;
    int row0 = blockIdx.x * 32;

    const float4* W4  = (const float4*)W;
    float4*       Ws4 = (float4*)Ws;
#pragma unroll
    for (int i = 0; i < 16; i++) Ws4[tid + 256 * i] = W4[tid + 256 * i];
#pragma unroll
    for (int i = 0; i < 4; i++) {
        int idx = tid + 256 * i;           // 0..1023
        int r = idx >> 5, c4 = idx & 31;
        int n = row0 + r;
        float4 v = (n < N) ? ((const float4*)X)[(size_t)n * C4 + c4]
                           : make_float4(0.f, 0.f, 0.f, 0.f);
        Xs[r * 129 + c4 * 4 + 0] = v.x;
        Xs[r * 129 + c4 * 4 + 1] = v.y;
        Xs[r * 129 + c4 * 4 + 2] = v.z;
        Xs[r * 129 + c4 * 4 + 3] = v.w;
    }
    __syncthreads();

    int row = tid >> 3, cg = tid & 7;
    int n = row0 + row;
    unsigned long long acc[8];
#pragma unroll
    for (int j = 0; j < 8; j++) acc[j] = 0ull;

#pragma unroll 4
    for (int k = 0; k < C; k++) {
        unsigned xu = __float_as_uint(Xs[row * 129 + k]);
        unsigned long long xp;
        asm("mov.b64 %0, {%1, %1};" : "=l"(xp) : "r"(xu));
        const unsigned long long* wrow = (const unsigned long long*)(Ws + k * C);
#pragma unroll
        for (int j = 0; j < 8; j++) {
            unsigned long long wp = wrow[cg + 8 * j];
            asm("fma.rn.f32x2 %0, %1, %2, %0;" : "+l"(acc[j]) : "l"(xp), "l"(wp));
        }
    }

    if (n >= N) return;
    float di = g_dinv[n];
    float d2 = di * di;
#pragma unroll
    for (int j = 0; j < 8; j++) {
        int col = 2 * cg + 16 * j;
        float lo = __uint_as_float((unsigned)(acc[j] & 0xffffffffull));
        float hi = __uint_as_float((unsigned)(acc[j] >> 32));
        *(float2*)(g_xw + (size_t)n * C + col) = make_float2(lo, hi);
        float b0 = bias[col], b1 = bias[col + 1];
        *(float2*)(g_agg + (size_t)n * C + col) =
            make_float2(fmaf(lo, d2, b0), fmaf(hi, d2, b1));
    }
}

// ---------------- edge scatter: agg[dst] += xw[src] * dinv[src]*dinv[dst] ----------
// One warp per edge, each lane handles 4 channels via float4 gather + vector RED.
__global__ void k_scatter(const int* __restrict__ ei, int E) {
    int t = blockIdx.x * 256 + threadIdx.x;
    int e = t >> 5;
    if (e >= E) return;
    int lane = t & 31;
    int s = ei[e], d = ei[E + e];
    float norm = g_dinv[s] * g_dinv[d];
    float4 v = ((const float4*)g_xw)[(size_t)s * C4 + lane];
    float* p = g_agg + (size_t)d * C + lane * 4;
    asm volatile("red.global.add.v4.f32 [%0], {%1, %2, %3, %4};"
                 :: "l"(p), "f"(v.x * norm), "f"(v.y * norm),
                    "f"(v.z * norm), "f"(v.w * norm)
                 : "memory");
}

// ---------------- GraphNorm statistics ----------------
__global__ void k_zero_stats() {
    int i = blockIdx.x * blockDim.x + threadIdx.x;
    if (i < GMAX * C) { g_ssum[i] = 0.f; g_ssq[i] = 0.f; }
}

// 128 threads (one per channel), 256 nodes per block. batch is sorted, so we
// accumulate in registers and flush to global atomics only on graph change.
__global__ void k_reduce(const int* __restrict__ batch, int N) {
    __shared__ int bs[256];
    int c  = threadIdx.x;   // channel
    int n0 = blockIdx.x * 256;
    for (int i = c; i < 256; i += 128) {
        int n = n0 + i;
        bs[i] = (n < N) ? batch[n] : -1;
    }
    __syncthreads();
    int lim = N - n0; if (lim > 256) lim = 256;
    if (lim <= 0) return;
    float s = 0.f, q = 0.f;
    int gcur = bs[0];
    for (int i = 0; i < lim; i++) {
        int g = bs[i];
        if (g != gcur) {
            atomicAdd(&g_ssum[gcur * C + c], s);
            atomicAdd(&g_ssq [gcur * C + c], q);
            s = 0.f; q = 0.f; gcur = g;
        }
        float v = g_agg[(size_t)(n0 + i) * C + c];
        s += v;
        q = fmaf(v, v, q);
    }
    atomicAdd(&g_ssum[gcur * C + c], s);
    atomicAdd(&g_ssq [gcur * C + c], q);
}

// var(out) with out = x - mu*s:  E[x^2] - mu^2*(2s - s^2). Fold everything
// into per-(graph,channel) affine y = x*A + B.
__global__ void k_stats(const float* __restrict__ gnw, const float* __restrict__ gnb,
                        const float* __restrict__ gms) {
    int i = blockIdx.x * blockDim.x + threadIdx.x;
    if (i >= GMAX * C) return;
    int g = i >> 7, c = i & (C - 1);
    float ci  = g_cntinv[g];
    float mu  = g_ssum[i] * ci;
    float m2  = g_ssq [i] * ci;
    float sc  = gms[c];
    float var = m2 - mu * mu * (2.f * sc - sc * sc);
    float rstd = rsqrtf(var + EPSV);
    float A = rstd * gnw[c];
    g_A[i] = A;
    g_B[i] = gnb[c] - mu * sc * A;
    (void)g;
}

// ---------------- norm + leaky relu + write history (and final x) ----------------
__global__ void k_norm(const int* __restrict__ batch, float* __restrict__ hist,
                       float* __restrict__ fin, int N) {
    int t = blockIdx.x * blockDim.x + threadIdx.x;
    int n = t >> 5;
    if (n >= N) return;
    int c4 = t & 31;
    int g = batch[n];
    float4 v = ((const float4*)g_agg)[(size_t)n * C4 + c4];
    float4 a = ((const float4*)g_A)[g * C4 + c4];
    float4 b = ((const float4*)g_B)[g * C4 + c4];
    float4 y;
    y.x = fmaf(v.x, a.x, b.x); y.x = fmaxf(y.x, NEG * y.x);
    y.y = fmaf(v.y, a.y, b.y); y.y = fmaxf(y.y, NEG * y.y);
    y.z = fmaf(v.z, a.z, b.z); y.z = fmaxf(y.z, NEG * y.z);
    y.w = fmaf(v.w, a.w, b.w); y.w = fmaxf(y.w, NEG * y.w);
    ((float4*)hist)[(size_t)n * C4 + c4] = y;
    if (fin) ((float4*)fin)[(size_t)n * C4 + c4] = y;
}

// ---------------- launch ----------------
extern "C" void kernel_launch(void* const* d_in, const int* in_sizes, int n_in,
                              void* d_out, int out_size) {
    const float* x     = (const float*)d_in[0];
    const int*   ei    = (const int*)d_in[1];
    const int*   batch = (const int*)d_in[2];
    const float* W     = (const float*)d_in[3];
    const float* b     = (const float*)d_in[4];
    const float* gnw   = (const float*)d_in[5];
    const float* gnb   = (const float*)d_in[6];
    const float* gms   = (const float*)d_in[7];
    float* out = (float*)d_out;

    int N = in_sizes[0] / C;
    int E = in_sizes[1] / 2;
    size_t NC = (size_t)N * C;

    int zb = (N + 255) / 256;
    k_zero_prep<<<zb, 256>>>(N);
    int cm = (E > N ? E : N);
    k_count<<<(cm + 255) / 256, 256>>>(ei, batch, E, N);
    k_finprep<<<zb, 256>>>(N);

    const float* xin = x;
    for (int l = 0; l < LNUM; l++) {
        k_gemm<<<(N + 31) / 32, 256>>>(xin, W + (size_t)l * C * C, b + (size_t)l * C, N);
        k_zero_stats<<<(GMAX * C + 255) / 256, 256>>>();
        k_scatter<<<(E * 32 + 255) / 256, 256>>>(ei, E);
        k_reduce<<<(N + 255) / 256, 128>>>(batch, N);
        k_stats<<<(GMAX * C + 255) / 256, 256>>>(gnw + (size_t)l * C,
                                                 gnb + (size_t)l * C,
                                                 gms + (size_t)l * C);
        float* hist = out + NC * (size_t)(1 + l);
        float* fin  = (l == LNUM - 1) ? out : nullptr;
        k_norm<<<((size_t)N * 32 + 255) / 256, 256>>>(batch, hist, fin, N);
        xin = hist;
    }
}

// round 2
// speedup vs baseline: 1.1204x; 1.1204x over previous
#include <cuda_runtime.h>
#include <cstdint>

#define C      128
#define C4     32
#define GMAX   64
#define LNUM   3
#define NCAP   100000
#define NEG    0.01f
#define EPSV   1e-5f

typedef unsigned long long ull;

// ---------------- static scratch ----------------
__device__ float g_xw  [(size_t)NCAP * C];   // (x @ W) * dinv  (pre-scaled for scatter)
__device__ float g_agg [(size_t)NCAP * C];   // aggregation buffer (init = xw*dinv^2 + b)
__device__ float g_deg [NCAP];
__device__ float g_dinv[NCAP];
__device__ float g_cnt   [GMAX];
__device__ float g_cntinv[GMAX];
__device__ float g_ssum[GMAX * C];
__device__ float g_ssq [GMAX * C];
__device__ float g_A   [GMAX * C];
__device__ float g_B   [GMAX * C];

// ---------------- prep ----------------
__global__ void k_zero_prep(int N) {
    int i = blockIdx.x * blockDim.x + threadIdx.x;
    if (i < N)    g_deg[i] = 0.f;
    if (i < GMAX) g_cnt[i] = 0.f;
}

__global__ void k_count(const int* __restrict__ ei, const int* __restrict__ batch,
                        int E, int N) {
    int i = blockIdx.x * blockDim.x + threadIdx.x;
    if (i < E) atomicAdd(&g_deg[ei[E + i]], 1.0f);
    if (i < N) atomicAdd(&g_cnt[batch[i]], 1.0f);
}

__global__ void k_finprep(int N) {
    int i = blockIdx.x * blockDim.x + threadIdx.x;
    if (i < N)    g_dinv[i]   = rsqrtf(g_deg[i] + 1.0f);
    if (i < GMAX) g_cntinv[i] = 1.0f / fmaxf(g_cnt[i], 1.0f);
}

// ---------------- GEMM ----------------
// Block 256 threads, tile 64 rows x 128 cols, K=128 resident.
// Thread (tx=tid&15, ty=tid>>4): 4 rows x 8 cols via fma.rn.f32x2.
// X tile stored in smem PRE-DUPLICATED as (x,x) 64-bit pairs so each
// LDS.128 yields two packed broadcast operands (no per-k mov.b64).
__device__ __forceinline__ ull dupf(float v) {
    ull r; unsigned u = __float_as_uint(v);
    asm("mov.b64 %0, {%1, %1};" : "=l"(r) : "r"(u));
    return r;
}
__device__ __forceinline__ float2 unpack(ull p) {
    float2 r;
    asm("mov.b64 {%0, %1}, %2;" : "=f"(r.x), "=f"(r.y) : "l"(p));
    return r;
}

__global__ void __launch_bounds__(256, 1)
k_gemm(const float* __restrict__ X, const float* __restrict__ W,
       const float* __restrict__ bias, int N) {
    extern __shared__ char smraw[];
    ull*   Xd = (ull*)smraw;                       // [64][128] dup pairs: 64KB
    float* Ws = (float*)(smraw + 64 * 128 * 8);    // [128][128]: 64KB

    int tid  = threadIdx.x;
    int row0 = blockIdx.x * 64;

    // load W -> smem
    const float4* W4  = (const float4*)W;
    float4*       Ws4 = (float4*)Ws;
#pragma unroll
    for (int i = 0; i < 16; i++) Ws4[tid + 256 * i] = W4[tid + 256 * i];

    // load X tile, duplicate each float into a (x,x) 64-bit pair
    const float4* X4 = (const float4*)X;
#pragma unroll
    for (int i = 0; i < 8; i++) {
        int idx = tid + 256 * i;            // 0..2047 = 64 rows * 32 float4
        int r = idx >> 5, c4 = idx & 31;
        int n = row0 + r;
        float4 v = (n < N) ? X4[(size_t)n * C4 + c4] : make_float4(0.f, 0.f, 0.f, 0.f);
        ulonglong2* dst = (ulonglong2*)(Xd + (size_t)r * 128 + c4 * 4);
        ulonglong2 p0; p0.x = dupf(v.x); p0.y = dupf(v.y);
        ulonglong2 p1; p1.x = dupf(v.z); p1.y = dupf(v.w);
        dst[0] = p0; dst[1] = p1;
    }
    __syncthreads();

    int tx = tid & 15, ty = tid >> 4;
    int c0 = tx * 8;

    ull acc[4][4];
#pragma unroll
    for (int i = 0; i < 4; i++)
#pragma unroll
        for (int j = 0; j < 4; j++) acc[i][j] = 0ull;

    const ulonglong2* xr0 = (const ulonglong2*)(Xd + (size_t)(ty * 4 + 0) * 128);
    const ulonglong2* xr1 = (const ulonglong2*)(Xd + (size_t)(ty * 4 + 1) * 128);
    const ulonglong2* xr2 = (const ulonglong2*)(Xd + (size_t)(ty * 4 + 2) * 128);
    const ulonglong2* xr3 = (const ulonglong2*)(Xd + (size_t)(ty * 4 + 3) * 128);

#pragma unroll 4
    for (int kp = 0; kp < 64; kp++) {          // kp covers k = 2kp, 2kp+1
        ulonglong2 xv[4];
        xv[0] = xr0[kp]; xv[1] = xr1[kp]; xv[2] = xr2[kp]; xv[3] = xr3[kp];
#pragma unroll
        for (int h = 0; h < 2; h++) {
            int k = 2 * kp + h;
            const ulonglong2* wrow = (const ulonglong2*)(Ws + (size_t)k * 128 + c0);
            ulonglong2 wa = wrow[0];
            ulonglong2 wb = wrow[1];
#pragma unroll
            for (int i = 0; i < 4; i++) {
                ull xp = h ? xv[i].y : xv[i].x;
                asm("fma.rn.f32x2 %0, %1, %2, %0;" : "+l"(acc[i][0]) : "l"(xp), "l"(wa.x));
                asm("fma.rn.f32x2 %0, %1, %2, %0;" : "+l"(acc[i][1]) : "l"(xp), "l"(wa.y));
                asm("fma.rn.f32x2 %0, %1, %2, %0;" : "+l"(acc[i][2]) : "l"(xp), "l"(wb.x));
                asm("fma.rn.f32x2 %0, %1, %2, %0;" : "+l"(acc[i][3]) : "l"(xp), "l"(wb.y));
            }
        }
    }

    // epilogue: g_xw = xw*dinv ; g_agg = xw*dinv^2 + bias
    float4 blo = *(const float4*)(bias + c0);
    float4 bhi = *(const float4*)(bias + c0 + 4);
#pragma unroll
    for (int i = 0; i < 4; i++) {
        int n = row0 + ty * 4 + i;
        if (n >= N) continue;
        float di = g_dinv[n];
        float2 a0 = unpack(acc[i][0]), a1 = unpack(acc[i][1]);
        float2 a2 = unpack(acc[i][2]), a3 = unpack(acc[i][3]);
        float4 lo = make_float4(a0.x * di, a0.y * di, a1.x * di, a1.y * di);
        float4 hi = make_float4(a2.x * di, a2.y * di, a3.x * di, a3.y * di);
        *(float4*)(g_xw + (size_t)n * C + c0)     = lo;
        *(float4*)(g_xw + (size_t)n * C + c0 + 4) = hi;
        float4 glo = make_float4(fmaf(lo.x, di, blo.x), fmaf(lo.y, di, blo.y),
                                 fmaf(lo.z, di, blo.z), fmaf(lo.w, di, blo.w));
        float4 ghi = make_float4(fmaf(hi.x, di, bhi.x), fmaf(hi.y, di, bhi.y),
                                 fmaf(hi.z, di, bhi.z), fmaf(hi.w, di, bhi.w));
        *(float4*)(g_agg + (size_t)n * C + c0)     = glo;
        *(float4*)(g_agg + (size_t)n * C + c0 + 4) = ghi;
    }
}

// ---------------- edge scatter ----------------
// g_xw is pre-scaled by dinv[src]; only dinv[dst] needed here.
__global__ void k_scatter(const int* __restrict__ ei, int E) {
    int t = blockIdx.x * 256 + threadIdx.x;
    int e = t >> 5;
    if (e >= E) return;
    int lane = t & 31;
    int s = ei[e], d = ei[E + e];
    float norm = g_dinv[d];
    float4 v = ((const float4*)g_xw)[(size_t)s * C4 + lane];
    float* p = g_agg + (size_t)d * C + lane * 4;
    asm volatile("red.global.add.v4.f32 [%0], {%1, %2, %3, %4};"
                 :: "l"(p), "f"(v.x * norm), "f"(v.y * norm),
                    "f"(v.z * norm), "f"(v.w * norm)
                 : "memory");
}

// ---------------- GraphNorm statistics ----------------
__global__ void k_zero_stats() {
    int i = blockIdx.x * blockDim.x + threadIdx.x;
    if (i < GMAX * C) { g_ssum[i] = 0.f; g_ssq[i] = 0.f; }
}

__global__ void k_reduce(const int* __restrict__ batch, int N) {
    __shared__ int bs[256];
    int c  = threadIdx.x;
    int n0 = blockIdx.x * 256;
    for (int i = c; i < 256; i += 128) {
        int n = n0 + i;
        bs[i] = (n < N) ? batch[n] : -1;
    }
    __syncthreads();
    int lim = N - n0; if (lim > 256) lim = 256;
    if (lim <= 0) return;
    float s = 0.f, q = 0.f;
    int gcur = bs[0];
    for (int i = 0; i < lim; i++) {
        int g = bs[i];
        if (g != gcur) {
            atomicAdd(&g_ssum[gcur * C + c], s);
            atomicAdd(&g_ssq [gcur * C + c], q);
            s = 0.f; q = 0.f; gcur = g;
        }
        float v = g_agg[(size_t)(n0 + i) * C + c];
        s += v;
        q = fmaf(v, v, q);
    }
    atomicAdd(&g_ssum[gcur * C + c], s);
    atomicAdd(&g_ssq [gcur * C + c], q);
}

__global__ void k_stats(const float* __restrict__ gnw, const float* __restrict__ gnb,
                        const float* __restrict__ gms) {
    int i = blockIdx.x * blockDim.x + threadIdx.x;
    if (i >= GMAX * C) return;
    int g = i >> 7, c = i & (C - 1);
    float ci  = g_cntinv[g];
    float mu  = g_ssum[i] * ci;
    float m2  = g_ssq [i] * ci;
    float sc  = gms[c];
    float var = m2 - mu * mu * (2.f * sc - sc * sc);
    float rstd = rsqrtf(var + EPSV);
    float A = rstd * gnw[c];
    g_A[i] = A;
    g_B[i] = gnb[c] - mu * sc * A;
}

// ---------------- norm + leaky relu + history ----------------
__global__ void k_norm(const int* __restrict__ batch, float* __restrict__ hist,
                       float* __restrict__ fin, int N) {
    int t = blockIdx.x * blockDim.x + threadIdx.x;
    int n = t >> 5;
    if (n >= N) return;
    int c4 = t & 31;
    int g = batch[n];
    float4 v = ((const float4*)g_agg)[(size_t)n * C4 + c4];
    float4 a = ((const float4*)g_A)[g * C4 + c4];
    float4 b = ((const float4*)g_B)[g * C4 + c4];
    float4 y;
    y.x = fmaf(v.x, a.x, b.x); y.x = fmaxf(y.x, NEG * y.x);
    y.y = fmaf(v.y, a.y, b.y); y.y = fmaxf(y.y, NEG * y.y);
    y.z = fmaf(v.z, a.z, b.z); y.z = fmaxf(y.z, NEG * y.z);
    y.w = fmaf(v.w, a.w, b.w); y.w = fmaxf(y.w, NEG * y.w);
    ((float4*)hist)[(size_t)n * C4 + c4] = y;
    if (fin) ((float4*)fin)[(size_t)n * C4 + c4] = y;
}

// ---------------- launch ----------------
extern "C" void kernel_launch(void* const* d_in, const int* in_sizes, int n_in,
                              void* d_out, int out_size) {
    const float* x     = (const float*)d_in[0];
    const int*   ei    = (const int*)d_in[1];
    const int*   batch = (const int*)d_in[2];
    const float* W     = (const float*)d_in[3];
    const float* b     = (const float*)d_in[4];
    const float* gnw   = (const float*)d_in[5];
    const float* gnb   = (const float*)d_in[6];
    const float* gms   = (const float*)d_in[7];
    float* out = (float*)d_out;

    int N = in_sizes[0] / C;
    int E = in_sizes[1] / 2;
    size_t NC = (size_t)N * C;

    const int GEMM_SMEM = 64 * 128 * 8 + 128 * 128 * 4;   // 128 KB
    static int smem_set = 0;
    if (!smem_set) {
        cudaFuncSetAttribute(k_gemm, cudaFuncAttributeMaxDynamicSharedMemorySize,
                             GEMM_SMEM);
        smem_set = 1;
    }

    int zb = (N + 255) / 256;
    k_zero_prep<<<zb, 256>>>(N);
    int cm = (E > N ? E : N);
    k_count<<<(cm + 255) / 256, 256>>>(ei, batch, E, N);
    k_finprep<<<zb, 256>>>(N);

    const float* xin = x;
    for (int l = 0; l < LNUM; l++) {
        k_gemm<<<(N + 63) / 64, 256, GEMM_SMEM>>>(xin, W + (size_t)l * C * C,
                                                  b + (size_t)l * C, N);
        k_zero_stats<<<(GMAX * C + 255) / 256, 256>>>();
        k_scatter<<<(E * 32 + 255) / 256, 256>>>(ei, E);
        k_reduce<<<(N + 255) / 256, 128>>>(batch, N);
        k_stats<<<(GMAX * C + 255) / 256, 256>>>(gnw + (size_t)l * C,
                                                 gnb + (size_t)l * C,
                                                 gms + (size_t)l * C);
        float* hist = out + NC * (size_t)(1 + l);
        float* fin  = (l == LNUM - 1) ? out : nullptr;
        k_norm<<<((size_t)N * 32 + 255) / 256, 256>>>(batch, hist, fin, N);
        xin = hist;
    }
}